// round 1
// baseline (speedup 1.0000x reference)
#include <cuda_runtime.h>
#include <cstdint>
#include <cmath>

// Problem dims
#define NB   4096   // batch
#define DOBS 256
#define DH   1024
#define DOUT 256
#define NTT  20     // time grid length

// GEMM tile config
#define BM 128
#define BN 128
#define BK 32
#define LDA_S 36    // padded smem stride for A (conflict-free fragment reads)
#define LDB_S 132   // padded smem stride for B

// Epilogue modes
//  0: out1 = v + bias[col]                       (xW precompute / final out GEMM)
//  1: out1 = tanh(v + bias[col])                 (f inner GEMM)
//  2: k=v+bias; acc=hb+ca*k; arg=hb+cb*k         (RK stage 1)
//  3: k=v+bias; acc+=ca*k;  arg=hb+cb*k          (RK stages 2,3)
//  4: k=v+bias; hcur = accIn + ca*k              (RK stage 4)
//  5: out1 = sigmoid(v + xw)                     (gate)
//  6: ct=sigmoid(v+xw); cn=g*(c+ct); hn=g*tanh(cn); write cn,hn,hn (c_tilde fused LSTM)
struct EpiParams {
    const float* bias;
    const float* tgrid;
    int   step;
    float fa, fb;
    const float* aux1;   // hbase / acc-in / xw
    const float* aux2;   // gate
    const float* aux3;   // c
    float* out1;
    float* out2;
    float* out3;
    int mode;
};

// Scratch (device globals — no allocation allowed)
__device__ float g_xw  [(size_t)NB * DH];
__device__ float g_gate[(size_t)NB * DH];
__device__ float g_hcur[(size_t)NB * DH];
__device__ float g_acc [(size_t)NB * DH];
__device__ float g_arg [(size_t)NB * DH];
__device__ float g_u   [(size_t)NB * DH];
__device__ float g_hbuf[(size_t)NB * DH];

__device__ __forceinline__ uint32_t f2tf32(float x) {
    uint32_t r;
    asm("cvt.rna.tf32.f32 %0, %1;" : "=r"(r) : "f"(x));
    return r;
}

__device__ __forceinline__ void mma_tf32(float c[4], const uint32_t a[4], const uint32_t b[2]) {
    asm volatile(
        "mma.sync.aligned.m16n8k8.row.col.f32.tf32.tf32.f32 "
        "{%0,%1,%2,%3}, {%4,%5,%6,%7}, {%8,%9}, {%0,%1,%2,%3};"
        : "+f"(c[0]), "+f"(c[1]), "+f"(c[2]), "+f"(c[3])
        : "r"(a[0]), "r"(a[1]), "r"(a[2]), "r"(a[3]), "r"(b[0]), "r"(b[1]));
}

// C[M=4096, N] (+epilogue) = A[4096, K] (row-major, ld=K) * W[K, N] (row-major, ld=ldw)
__global__ __launch_bounds__(256, 2) void gemm_epi(
    const float* __restrict__ A, const float* __restrict__ W,
    int K, int ldw, int N, EpiParams ep)
{
    __shared__ uint32_t As[BM * LDA_S];
    __shared__ uint32_t Bs[BK * LDB_S];

    const int m0 = blockIdx.y * BM;
    const int n0 = blockIdx.x * BN;
    const int tid  = threadIdx.x;
    const int lane = tid & 31;
    const int wid  = tid >> 5;
    const int wm = (wid & 3) * 32;   // 4 warps along M
    const int wn = (wid >> 2) * 64;  // 2 warps along N

    float accr[2][8][4];
    #pragma unroll
    for (int i = 0; i < 2; i++)
        #pragma unroll
        for (int j = 0; j < 8; j++)
            #pragma unroll
            for (int k = 0; k < 4; k++) accr[i][j][k] = 0.f;

    for (int kt = 0; kt < K; kt += BK) {
        if (kt) __syncthreads();
        // Load A tile: 128 x 32 floats = 1024 float4
        for (int i = tid; i < (BM * BK / 4); i += 256) {
            int r = i >> 3, cf = i & 7;
            float4 v = *(const float4*)(A + (size_t)(m0 + r) * K + kt + cf * 4);
            uint32_t* p = &As[r * LDA_S + cf * 4];
            p[0] = f2tf32(v.x); p[1] = f2tf32(v.y); p[2] = f2tf32(v.z); p[3] = f2tf32(v.w);
        }
        // Load B tile: 32 x 128 floats = 1024 float4
        for (int i = tid; i < (BK * BN / 4); i += 256) {
            int r = i >> 5, cf = i & 31;
            float4 v = *(const float4*)(W + (size_t)(kt + r) * ldw + n0 + cf * 4);
            uint32_t* p = &Bs[r * LDB_S + cf * 4];
            p[0] = f2tf32(v.x); p[1] = f2tf32(v.y); p[2] = f2tf32(v.z); p[3] = f2tf32(v.w);
        }
        __syncthreads();

        #pragma unroll
        for (int k8 = 0; k8 < 4; k8++) {
            uint32_t af[2][4];
            #pragma unroll
            for (int mt = 0; mt < 2; mt++) {
                int r  = wm + mt * 16 + (lane >> 2);
                int cc = k8 * 8 + (lane & 3);
                af[mt][0] = As[r * LDA_S + cc];
                af[mt][1] = As[(r + 8) * LDA_S + cc];
                af[mt][2] = As[r * LDA_S + cc + 4];
                af[mt][3] = As[(r + 8) * LDA_S + cc + 4];
            }
            uint32_t bf[8][2];
            #pragma unroll
            for (int nt = 0; nt < 8; nt++) {
                int kk = k8 * 8 + (lane & 3);
                int nn = wn + nt * 8 + (lane >> 2);
                bf[nt][0] = Bs[kk * LDB_S + nn];
                bf[nt][1] = Bs[(kk + 4) * LDB_S + nn];
            }
            #pragma unroll
            for (int mt = 0; mt < 2; mt++)
                #pragma unroll
                for (int nt = 0; nt < 8; nt++)
                    mma_tf32(accr[mt][nt], af[mt], bf[nt]);
        }
    }

    // Epilogue
    float ca = 0.f, cb = 0.f;
    if (ep.mode >= 2 && ep.mode <= 4) {
        float dt = ep.tgrid[ep.step + 1] - ep.tgrid[ep.step];
        ca = ep.fa * dt;
        cb = ep.fb * dt;
    }

    #pragma unroll
    for (int mt = 0; mt < 2; mt++)
        #pragma unroll
        for (int nt = 0; nt < 8; nt++)
            #pragma unroll
            for (int ci = 0; ci < 4; ci++) {
                int row = m0 + wm + mt * 16 + (lane >> 2) + ((ci & 2) << 2);
                int col = n0 + wn + nt * 8 + ((lane & 3) << 1) + (ci & 1);
                size_t idx = (size_t)row * N + col;
                float v = accr[mt][nt][ci];
                switch (ep.mode) {
                    case 0: ep.out1[idx] = v + ep.bias[col]; break;
                    case 1: ep.out1[idx] = tanhf(v + ep.bias[col]); break;
                    case 2: {
                        float k = v + ep.bias[col];
                        float hb = ep.aux1[idx];
                        ep.out1[idx] = hb + ca * k;
                        ep.out2[idx] = hb + cb * k;
                    } break;
                    case 3: {
                        float k = v + ep.bias[col];
                        float hb = ep.aux1[idx];
                        ep.out1[idx] += ca * k;
                        ep.out2[idx] = hb + cb * k;
                    } break;
                    case 4: {
                        float k = v + ep.bias[col];
                        ep.out1[idx] = ep.aux1[idx] + ca * k;
                    } break;
                    case 5: {
                        float pre = v + ep.aux1[idx];
                        ep.out1[idx] = 1.f / (1.f + expf(-pre));
                    } break;
                    case 6: {
                        float pre = v + ep.aux1[idx];
                        float ct = 1.f / (1.f + expf(-pre));
                        float g = ep.aux2[idx];
                        float cn = g * (ep.aux3[idx] + ct);
                        float hn = g * tanhf(cn);
                        ep.out1[idx] = cn;   // c_new
                        ep.out2[idx] = hn;   // h_new (d_out)
                        ep.out3[idx] = hn;   // h_new scratch for out GEMM
                    } break;
                }
            }
}

static inline void run_gemm(const float* A, const float* W, int K, int ldw, int N,
                            const EpiParams& ep) {
    dim3 grid(N / BN, NB / BM), blk(256);
    gemm_epi<<<grid, blk>>>(A, W, K, ldw, N, ep);
}

extern "C" void kernel_launch(void* const* d_in, const int* in_sizes, int n_in,
                              void* d_out, int out_size) {
    const float* x     = (const float*)d_in[0];
    const float* h     = (const float*)d_in[1];
    const float* c     = (const float*)d_in[2];
    const float* t     = (const float*)d_in[3];
    const float* W_i2h = (const float*)d_in[4];
    const float* b_i2h = (const float*)d_in[5];
    const float* W_h2o = (const float*)d_in[6];
    const float* b_h2o = (const float*)d_in[7];
    const float* Wf1   = (const float*)d_in[8];
    const float* bf1   = (const float*)d_in[9];
    const float* Wf2   = (const float*)d_in[10];
    const float* bf2   = (const float*)d_in[11];

    float* out   = (float*)d_out;
    float* out_o = out;                                  // [NB, DOUT]
    float* out_h = out + (size_t)NB * DOUT;              // [NB, DH]
    float* out_c = out + (size_t)NB * DOUT + (size_t)NB * DH;  // [NB, DH]

    float *xw, *gate, *hcur, *acc, *arg, *u, *hbuf;
    cudaGetSymbolAddress((void**)&xw,   g_xw);
    cudaGetSymbolAddress((void**)&gate, g_gate);
    cudaGetSymbolAddress((void**)&hcur, g_hcur);
    cudaGetSymbolAddress((void**)&acc,  g_acc);
    cudaGetSymbolAddress((void**)&arg,  g_arg);
    cudaGetSymbolAddress((void**)&u,    g_u);
    cudaGetSymbolAddress((void**)&hbuf, g_hbuf);

    const float* W_bot = W_i2h + (size_t)DOBS * DH;  // rows 256..1279 of W_i2h

    // 1) xw = x @ W_i2h[:256] + b_i2h   (shared by gate and c_tilde)
    {
        EpiParams ep{}; ep.bias = b_i2h; ep.out1 = xw; ep.mode = 0;
        run_gemm(x, W_i2h, DOBS, DH, DH, ep);
    }
    // 2) gate = sigmoid(xw + h @ W_bot)
    {
        EpiParams ep{}; ep.aux1 = xw; ep.out1 = gate; ep.mode = 5;
        run_gemm(h, W_bot, DH, DH, DH, ep);
    }
    // 3) RK4 over the time grid: h_ode in g_hcur
    for (int s = 0; s < NTT - 1; s++) {
        const float* hb = (s == 0) ? h : hcur;
        // stage 1: k1 = f(hb)
        { EpiParams ep{}; ep.bias = bf1; ep.out1 = u; ep.mode = 1;
          run_gemm(hb, Wf1, DH, DH, DH, ep); }
        { EpiParams ep{}; ep.bias = bf2; ep.tgrid = t; ep.step = s;
          ep.fa = 1.f / 6.f; ep.fb = 0.5f; ep.aux1 = hb;
          ep.out1 = acc; ep.out2 = arg; ep.mode = 2;
          run_gemm(u, Wf2, DH, DH, DH, ep); }
        // stage 2: k2 = f(arg)
        { EpiParams ep{}; ep.bias = bf1; ep.out1 = u; ep.mode = 1;
          run_gemm(arg, Wf1, DH, DH, DH, ep); }
        { EpiParams ep{}; ep.bias = bf2; ep.tgrid = t; ep.step = s;
          ep.fa = 1.f / 3.f; ep.fb = 0.5f; ep.aux1 = hb;
          ep.out1 = acc; ep.out2 = arg; ep.mode = 3;
          run_gemm(u, Wf2, DH, DH, DH, ep); }
        // stage 3: k3 = f(arg)
        { EpiParams ep{}; ep.bias = bf1; ep.out1 = u; ep.mode = 1;
          run_gemm(arg, Wf1, DH, DH, DH, ep); }
        { EpiParams ep{}; ep.bias = bf2; ep.tgrid = t; ep.step = s;
          ep.fa = 1.f / 3.f; ep.fb = 1.0f; ep.aux1 = hb;
          ep.out1 = acc; ep.out2 = arg; ep.mode = 3;
          run_gemm(u, Wf2, DH, DH, DH, ep); }
        // stage 4: k4 = f(arg); h_next = acc + dt/6 * k4
        { EpiParams ep{}; ep.bias = bf1; ep.out1 = u; ep.mode = 1;
          run_gemm(arg, Wf1, DH, DH, DH, ep); }
        { EpiParams ep{}; ep.bias = bf2; ep.tgrid = t; ep.step = s;
          ep.fa = 1.f / 6.f; ep.fb = 0.f; ep.aux1 = acc;
          ep.out1 = hcur; ep.mode = 4;
          run_gemm(u, Wf2, DH, DH, DH, ep); }
    }
    // 4) c_tilde GEMM with fused LSTM recombine: writes c_new, h_new into d_out + hbuf
    {
        EpiParams ep{}; ep.aux1 = xw; ep.aux2 = gate; ep.aux3 = c;
        ep.out1 = out_c; ep.out2 = out_h; ep.out3 = hbuf; ep.mode = 6;
        run_gemm(hcur, W_bot, DH, DH, DH, ep);
    }
    // 5) out = h_new @ W_h2o + b_h2o
    {
        EpiParams ep{}; ep.bias = b_h2o; ep.out1 = out_o; ep.mode = 0;
        run_gemm(hbuf, W_h2o, DH, DOUT, DOUT, ep);
    }
}

// round 4
// speedup vs baseline: 1.6607x; 1.6607x over previous
#include <cuda_runtime.h>
#include <cstdint>
#include <cmath>

// Problem dims
#define NB   4096
#define DOBS 256
#define DH   1024
#define DOUT 256
#define NTT  20

// GEMM tile config
#define BM 128
#define BN 128
#define BK 32
#define LDA_S 36    // padded smem stride (uint32 units) for A
#define LDB_S 132   // padded smem stride for B
#define A_STAGE_B (BM * LDA_S * 4)   // 18432 bytes
#define B_STAGE_B (BK * LDB_S * 4)   // 16896 bytes
#define SMEM_TOTAL (2 * (A_STAGE_B + B_STAGE_B))  // 70656

// Epilogue modes
//  0: out1 = v + bias[col]
//  1: out1 = tanh(v + bias[col])
//  2: k=v+bias; acc=hb+ca*k; arg=hb+cb*k
//  3: k=v+bias; acc+=ca*k;  arg=hb+cb*k
//  4: k=v+bias; hcur = accIn + ca*k
//  5: out1 = sigmoid(v + xw)
//  6: ct=sigmoid(v+xw); cn=g*(c+ct); hn=g*tanh(cn); write cn,hn,hn
struct EpiParams {
    const float* bias;
    const float* tgrid;
    int   step;
    float fa, fb;
    const float* aux1;
    const float* aux2;
    const float* aux3;
    float* out1;
    float* out2;
    float* out3;
    int mode;
};

// Scratch (device globals — no allocation allowed)
__device__ __align__(128) float g_xw  [(size_t)NB * DH];
__device__ __align__(128) float g_gate[(size_t)NB * DH];
__device__ __align__(128) float g_hcur[(size_t)NB * DH];
__device__ __align__(128) float g_acc [(size_t)NB * DH];
__device__ __align__(128) float g_arg [(size_t)NB * DH];
__device__ __align__(128) float g_u   [(size_t)NB * DH];
__device__ __align__(128) float g_hbuf[(size_t)NB * DH];
// tf32-pre-rounded weight copies (same layout as originals)
__device__ __align__(128) float g_wi2h[(size_t)(DOBS + DH) * DH];
__device__ __align__(128) float g_wf1 [(size_t)DH * DH];
__device__ __align__(128) float g_wf2 [(size_t)DH * DH];
__device__ __align__(128) float g_wh2o[(size_t)DH * DOUT];

__device__ __forceinline__ uint32_t f2tf32(float x) {
    uint32_t r;
    asm("cvt.rna.tf32.f32 %0, %1;" : "=r"(r) : "f"(x));
    return r;
}

__device__ __forceinline__ uint32_t smem_u32(const void* p) {
    uint32_t a;
    asm("{ .reg .u64 t; cvta.to.shared.u64 t, %1; cvt.u32.u64 %0, t; }"
        : "=r"(a) : "l"(p));
    return a;
}

__device__ __forceinline__ void cpa16(uint32_t s, const void* g) {
    asm volatile("cp.async.cg.shared.global [%0], [%1], 16;" :: "r"(s), "l"(g));
}
__device__ __forceinline__ void cpa_commit() {
    asm volatile("cp.async.commit_group;" ::: "memory");
}
__device__ __forceinline__ void cpa_wait0() {
    asm volatile("cp.async.wait_group 0;" ::: "memory");
}

__device__ __forceinline__ void mma_tf32(float c[4], const uint32_t a[4], const uint32_t b[2]) {
    asm volatile(
        "mma.sync.aligned.m16n8k8.row.col.f32.tf32.tf32.f32 "
        "{%0,%1,%2,%3}, {%4,%5,%6,%7}, {%8,%9}, {%0,%1,%2,%3};"
        : "+f"(c[0]), "+f"(c[1]), "+f"(c[2]), "+f"(c[3])
        : "r"(a[0]), "r"(a[1]), "r"(a[2]), "r"(a[3]), "r"(b[0]), "r"(b[1]));
}

__device__ __forceinline__ float sigm(float x) { return 1.f / (1.f + expf(-x)); }

// ---------------------------------------------------------------------------
// Weight pre-rounding: out[i] = tf32_rna(W[i])
// ---------------------------------------------------------------------------
__global__ void round_w(const float* __restrict__ W, float* __restrict__ out, int n) {
    int i = (blockIdx.x * blockDim.x + threadIdx.x) * 4;
    if (i < n) {
        float4 v = *(const float4*)(W + i);
        uint4 u;
        u.x = f2tf32(v.x); u.y = f2tf32(v.y); u.z = f2tf32(v.z); u.w = f2tf32(v.w);
        *(uint4*)(out + i) = u;
    }
}

// ---------------------------------------------------------------------------
// Pipelined tf32 mma.sync GEMM:
// C[M=4096, N] (+epi) = A[4096, K] (fp32, cvt after LDS) * W[K, N] (pre-rounded tf32)
// ---------------------------------------------------------------------------
__global__ __launch_bounds__(256, 2) void gemm_epi(
    const float* __restrict__ A, const float* __restrict__ W,
    int K, int ldw, int N, EpiParams ep)
{
    extern __shared__ char smem_raw[];
    uint32_t* const AsBase = (uint32_t*)smem_raw;
    uint32_t* const BsBase = (uint32_t*)(smem_raw + 2 * A_STAGE_B);

    const int m0 = blockIdx.y * BM;
    const int n0 = blockIdx.x * BN;
    const int tid  = threadIdx.x;
    const int lane = tid & 31;
    const int wid  = tid >> 5;
    const int wm = (wid & 3) * 32;   // 4 warps along M
    const int wn = (wid >> 2) * 64;  // 2 warps along N

    // Per-thread loader coordinates
    // A: 4 chunks; chunk i handles idx = tid + i*256; r = idx>>3, cf = idx&7
    // B: 4 chunks; r = idx>>5, cf = idx&31
    const int ar = tid >> 3, acf = tid & 7;       // + i*32 rows (256/8)
    const int br = tid >> 5, bcf = tid & 31;      // + i*8 rows (256/32)

    const float* Abase = A + (size_t)m0 * K;
    const float* Bbase = W + (size_t)n0;

    const uint32_t sA0 = smem_u32(AsBase);
    const uint32_t sB0 = smem_u32(BsBase);

    float accr[2][8][4];
    #pragma unroll
    for (int i = 0; i < 2; i++)
        #pragma unroll
        for (int j = 0; j < 8; j++)
            #pragma unroll
            for (int k = 0; k < 4; k++) accr[i][j][k] = 0.f;

    const int KT = K / BK;

    auto issue_tile = [&](int kt, int st) {
        const uint32_t sa = sA0 + st * A_STAGE_B;
        const uint32_t sb = sB0 + st * B_STAGE_B;
        const float* Ab = Abase + (size_t)kt * BK;
        const float* Bb = Bbase + (size_t)kt * BK * ldw;
        #pragma unroll
        for (int i = 0; i < 4; i++) {
            int r = ar + i * 32;
            cpa16(sa + (uint32_t)(r * LDA_S + acf * 4) * 4,
                  Ab + (size_t)r * K + acf * 4);
        }
        #pragma unroll
        for (int i = 0; i < 4; i++) {
            int r = br + i * 8;
            cpa16(sb + (uint32_t)(r * LDB_S + bcf * 4) * 4,
                  Bb + (size_t)r * ldw + bcf * 4);
        }
        cpa_commit();
    };

    issue_tile(0, 0);

    for (int kt = 0; kt < KT; kt++) {
        const int st = kt & 1;
        cpa_wait0();
        __syncthreads();
        if (kt + 1 < KT) issue_tile(kt + 1, (kt + 1) & 1);

        const uint32_t* As = AsBase + st * (A_STAGE_B / 4);
        const uint32_t* Bs = BsBase + st * (B_STAGE_B / 4);

        #pragma unroll
        for (int k8 = 0; k8 < 4; k8++) {
            uint32_t af[2][4];
            #pragma unroll
            for (int mt = 0; mt < 2; mt++) {
                int r  = wm + mt * 16 + (lane >> 2);
                int cc = k8 * 8 + (lane & 3);
                af[mt][0] = f2tf32(__uint_as_float(As[r * LDA_S + cc]));
                af[mt][1] = f2tf32(__uint_as_float(As[(r + 8) * LDA_S + cc]));
                af[mt][2] = f2tf32(__uint_as_float(As[r * LDA_S + cc + 4]));
                af[mt][3] = f2tf32(__uint_as_float(As[(r + 8) * LDA_S + cc + 4]));
            }
            uint32_t bf[8][2];
            #pragma unroll
            for (int nt = 0; nt < 8; nt++) {
                int kk = k8 * 8 + (lane & 3);
                int nn = wn + nt * 8 + (lane >> 2);
                bf[nt][0] = Bs[kk * LDB_S + nn];
                bf[nt][1] = Bs[(kk + 4) * LDB_S + nn];
            }
            #pragma unroll
            for (int mt = 0; mt < 2; mt++)
                #pragma unroll
                for (int nt = 0; nt < 8; nt++)
                    mma_tf32(accr[mt][nt], af[mt], bf[nt]);
        }
    }

    // ---------------- Epilogue ----------------
    float ca = 0.f, cb = 0.f;
    if (ep.mode >= 2 && ep.mode <= 4) {
        float dt = ep.tgrid[ep.step + 1] - ep.tgrid[ep.step];
        ca = ep.fa * dt;
        cb = ep.fb * dt;
    }

    #pragma unroll
    for (int mt = 0; mt < 2; mt++)
        #pragma unroll
        for (int nt = 0; nt < 8; nt++)
            #pragma unroll
            for (int ci = 0; ci < 4; ci++) {
                int row = m0 + wm + mt * 16 + (lane >> 2) + ((ci & 2) << 2);
                int col = n0 + wn + nt * 8 + ((lane & 3) << 1) + (ci & 1);
                size_t idx = (size_t)row * N + col;
                float v = accr[mt][nt][ci];
                switch (ep.mode) {
                    case 0: ep.out1[idx] = v + ep.bias[col]; break;
                    case 1: ep.out1[idx] = tanhf(v + ep.bias[col]); break;
                    case 2: {
                        float k = v + ep.bias[col];
                        float hb = ep.aux1[idx];
                        ep.out1[idx] = hb + ca * k;
                        ep.out2[idx] = hb + cb * k;
                    } break;
                    case 3: {
                        float k = v + ep.bias[col];
                        float hb = ep.aux1[idx];
                        ep.out1[idx] += ca * k;
                        ep.out2[idx] = hb + cb * k;
                    } break;
                    case 4: {
                        float k = v + ep.bias[col];
                        ep.out1[idx] = ep.aux1[idx] + ca * k;
                    } break;
                    case 5: {
                        float pre = v + ep.aux1[idx];
                        ep.out1[idx] = sigm(pre);
                    } break;
                    case 6: {
                        float pre = v + ep.aux1[idx];
                        float ct = sigm(pre);
                        float g = ep.aux2[idx];
                        float cn = g * (ep.aux3[idx] + ct);
                        float hn = g * tanhf(cn);
                        ep.out1[idx] = cn;
                        ep.out2[idx] = hn;
                        ep.out3[idx] = hn;
                    } break;
                }
            }
}

// ---------------------------------------------------------------------------
// Host orchestration
// ---------------------------------------------------------------------------
static inline void run_gemm(const float* A, const float* W, int K, int ldw, int N,
                            const EpiParams& ep) {
    dim3 grid(N / BN, NB / BM), blk(256);
    gemm_epi<<<grid, blk, SMEM_TOTAL>>>(A, W, K, ldw, N, ep);
}

extern "C" void kernel_launch(void* const* d_in, const int* in_sizes, int n_in,
                              void* d_out, int out_size) {
    const float* x     = (const float*)d_in[0];
    const float* h     = (const float*)d_in[1];
    const float* c     = (const float*)d_in[2];
    const float* t     = (const float*)d_in[3];
    const float* W_i2h = (const float*)d_in[4];
    const float* b_i2h = (const float*)d_in[5];
    const float* W_h2o = (const float*)d_in[6];
    const float* b_h2o = (const float*)d_in[7];
    const float* Wf1   = (const float*)d_in[8];
    const float* bf1   = (const float*)d_in[9];
    const float* Wf2   = (const float*)d_in[10];
    const float* bf2   = (const float*)d_in[11];

    float* out   = (float*)d_out;
    float* out_o = out;
    float* out_h = out + (size_t)NB * DOUT;
    float* out_c = out + (size_t)NB * DOUT + (size_t)NB * DH;

    cudaFuncSetAttribute(gemm_epi, cudaFuncAttributeMaxDynamicSharedMemorySize, SMEM_TOTAL);

    float *xw, *gate, *hcur, *acc, *arg, *u, *hbuf;
    float *wi2h, *wf1, *wf2, *wh2o;
    cudaGetSymbolAddress((void**)&xw,   g_xw);
    cudaGetSymbolAddress((void**)&gate, g_gate);
    cudaGetSymbolAddress((void**)&hcur, g_hcur);
    cudaGetSymbolAddress((void**)&acc,  g_acc);
    cudaGetSymbolAddress((void**)&arg,  g_arg);
    cudaGetSymbolAddress((void**)&u,    g_u);
    cudaGetSymbolAddress((void**)&hbuf, g_hbuf);
    cudaGetSymbolAddress((void**)&wi2h, g_wi2h);
    cudaGetSymbolAddress((void**)&wf1,  g_wf1);
    cudaGetSymbolAddress((void**)&wf2,  g_wf2);
    cudaGetSymbolAddress((void**)&wh2o, g_wh2o);

    // Pre-round weights to tf32 (rna) once per launch
    {
        int n1 = (DOBS + DH) * DH, n2 = DH * DH, n3 = DH * DOUT;
        round_w<<<n1 / 1024, 256>>>(W_i2h, wi2h, n1);
        round_w<<<n2 / 1024, 256>>>(Wf1,  wf1,  n2);
        round_w<<<n2 / 1024, 256>>>(Wf2,  wf2,  n2);
        round_w<<<n3 / 1024, 256>>>(W_h2o, wh2o, n3);
    }

    const float* wbot = wi2h + (size_t)DOBS * DH;  // rows 256.. of W_i2h

    // 1) xw = x @ W_i2h[:256] + b_i2h
    {
        EpiParams ep{}; ep.bias = b_i2h; ep.out1 = xw; ep.mode = 0;
        run_gemm(x, wi2h, DOBS, DH, DH, ep);
    }
    // 2) gate = sigmoid(xw + h @ W_bot)
    {
        EpiParams ep{}; ep.aux1 = xw; ep.out1 = gate; ep.mode = 5;
        run_gemm(h, wbot, DH, DH, DH, ep);
    }
    // 3) RK4
    for (int s = 0; s < NTT - 1; s++) {
        const float* hb = (s == 0) ? h : hcur;
        { EpiParams ep{}; ep.bias = bf1; ep.out1 = u; ep.mode = 1;
          run_gemm(hb, wf1, DH, DH, DH, ep); }
        { EpiParams ep{}; ep.bias = bf2; ep.tgrid = t; ep.step = s;
          ep.fa = 1.f / 6.f; ep.fb = 0.5f; ep.aux1 = hb;
          ep.out1 = acc; ep.out2 = arg; ep.mode = 2;
          run_gemm(u, wf2, DH, DH, DH, ep); }
        { EpiParams ep{}; ep.bias = bf1; ep.out1 = u; ep.mode = 1;
          run_gemm(arg, wf1, DH, DH, DH, ep); }
        { EpiParams ep{}; ep.bias = bf2; ep.tgrid = t; ep.step = s;
          ep.fa = 1.f / 3.f; ep.fb = 0.5f; ep.aux1 = hb;
          ep.out1 = acc; ep.out2 = arg; ep.mode = 3;
          run_gemm(u, wf2, DH, DH, DH, ep); }
        { EpiParams ep{}; ep.bias = bf1; ep.out1 = u; ep.mode = 1;
          run_gemm(arg, wf1, DH, DH, DH, ep); }
        { EpiParams ep{}; ep.bias = bf2; ep.tgrid = t; ep.step = s;
          ep.fa = 1.f / 3.f; ep.fb = 1.0f; ep.aux1 = hb;
          ep.out1 = acc; ep.out2 = arg; ep.mode = 3;
          run_gemm(u, wf2, DH, DH, DH, ep); }
        { EpiParams ep{}; ep.bias = bf1; ep.out1 = u; ep.mode = 1;
          run_gemm(arg, wf1, DH, DH, DH, ep); }
        { EpiParams ep{}; ep.bias = bf2; ep.tgrid = t; ep.step = s;
          ep.fa = 1.f / 6.f; ep.fb = 0.f; ep.aux1 = acc;
          ep.out1 = hcur; ep.mode = 4;
          run_gemm(u, wf2, DH, DH, DH, ep); }
    }
    // 4) c_tilde + fused LSTM recombine
    {
        EpiParams ep{}; ep.aux1 = xw; ep.aux2 = gate; ep.aux3 = c;
        ep.out1 = out_c; ep.out2 = out_h; ep.out3 = hbuf; ep.mode = 6;
        run_gemm(hcur, wbot, DH, DH, DH, ep);
    }
    // 5) out = h_new @ W_h2o + b_h2o
    {
        EpiParams ep{}; ep.bias = b_h2o; ep.out1 = out_o; ep.mode = 0;
        run_gemm(hbuf, wh2o, DH, DOUT, DOUT, ep);
    }
}

// round 5
// speedup vs baseline: 2.2483x; 1.3538x over previous
#include <cuda_runtime.h>
#include <cstdint>
#include <cmath>

// Problem dims
#define NB   4096
#define DOBS 256
#define DH   1024
#define DOUT 256
#define NTT  20

// GEMM tile config
#define BM 128
#define BN 128
#define BK 32
#define A_STAGE_B (BM * BK * 4)   // 16384 bytes (128 rows x 128B)
#define B_STAGE_B (BN * BK * 4)   // 16384 bytes (128 rows x 128B, n-major)
#define SMEM_TOTAL (2 * (A_STAGE_B + B_STAGE_B))  // 65536

// Epilogue modes
//  0: out1 = v + bias[col]
//  1: out1 = tanh(v + bias[col])
//  2: k=v+bias; acc=hb+ca*k; arg=hb+cb*k
//  3: k=v+bias; acc+=ca*k;  arg=hb+cb*k
//  4: k=v+bias; hcur = accIn + ca*k
//  5: out1 = sigmoid(v + xw)
//  6: ct=sigmoid(v+xw); cn=g*(c+ct); hn=g*tanh(cn); write cn,hn,hn
struct EpiParams {
    const float* bias;
    const float* tgrid;
    int   step;
    float fa, fb;
    const float* aux1;
    const float* aux2;
    const float* aux3;
    float* out1;
    float* out2;
    float* out3;
    int mode;
};

// Scratch (device globals — no allocation allowed)
__device__ __align__(128) float g_xw  [(size_t)NB * DH];
__device__ __align__(128) float g_gate[(size_t)NB * DH];
__device__ __align__(128) float g_hcur[(size_t)NB * DH];
__device__ __align__(128) float g_acc [(size_t)NB * DH];
__device__ __align__(128) float g_arg [(size_t)NB * DH];
__device__ __align__(128) float g_u   [(size_t)NB * DH];
__device__ __align__(128) float g_hbuf[(size_t)NB * DH];
// Transposed + tf32-rounded weights, [N, K] layout
__device__ __align__(128) float g_wi2hT[(size_t)DH * (DOBS + DH)];  // [1024, 1280]
__device__ __align__(128) float g_wf1T [(size_t)DH * DH];
__device__ __align__(128) float g_wf2T [(size_t)DH * DH];
__device__ __align__(128) float g_wh2oT[(size_t)DOUT * DH];         // [256, 1024]

__device__ __forceinline__ uint32_t f2tf32(float x) {
    uint32_t r;
    asm("cvt.rna.tf32.f32 %0, %1;" : "=r"(r) : "f"(x));
    return r;
}

__device__ __forceinline__ uint32_t smem_u32(const void* p) {
    uint32_t a;
    asm("{ .reg .u64 t; cvta.to.shared.u64 t, %1; cvt.u32.u64 %0, t; }"
        : "=r"(a) : "l"(p));
    return a;
}

__device__ __forceinline__ void cpa16(uint32_t s, const void* g) {
    asm volatile("cp.async.cg.shared.global [%0], [%1], 16;" :: "r"(s), "l"(g));
}
__device__ __forceinline__ void cpa_commit() {
    asm volatile("cp.async.commit_group;" ::: "memory");
}
__device__ __forceinline__ void cpa_wait0() {
    asm volatile("cp.async.wait_group 0;" ::: "memory");
}

__device__ __forceinline__ void ldsm_x4(uint32_t& r0, uint32_t& r1, uint32_t& r2,
                                        uint32_t& r3, uint32_t addr) {
    asm volatile("ldmatrix.sync.aligned.m8n8.x4.shared.b16 {%0,%1,%2,%3}, [%4];"
                 : "=r"(r0), "=r"(r1), "=r"(r2), "=r"(r3) : "r"(addr));
}

__device__ __forceinline__ void mma_tf32(float c[4], const uint32_t a[4], const uint32_t b[2]) {
    asm volatile(
        "mma.sync.aligned.m16n8k8.row.col.f32.tf32.tf32.f32 "
        "{%0,%1,%2,%3}, {%4,%5,%6,%7}, {%8,%9}, {%0,%1,%2,%3};"
        : "+f"(c[0]), "+f"(c[1]), "+f"(c[2]), "+f"(c[3])
        : "r"(a[0]), "r"(a[1]), "r"(a[2]), "r"(a[3]), "r"(b[0]), "r"(b[1]));
}

__device__ __forceinline__ float sigm(float x) { return 1.f / (1.f + expf(-x)); }

// ---------------------------------------------------------------------------
// Weight transpose + tf32 rna rounding: W[K,N] -> WT[N,K]
// ---------------------------------------------------------------------------
__global__ void transpose_cvt(const float* __restrict__ W, float* __restrict__ WT,
                              int K, int N) {
    __shared__ float tile[32][33];
    int n0 = blockIdx.x * 32, k0 = blockIdx.y * 32;
    int tx = threadIdx.x, ty = threadIdx.y;  // 32 x 8
    #pragma unroll
    for (int i = 0; i < 32; i += 8)
        tile[ty + i][tx] = W[(size_t)(k0 + ty + i) * N + n0 + tx];
    __syncthreads();
    #pragma unroll
    for (int i = 0; i < 32; i += 8) {
        float v = tile[tx][ty + i];  // = W[k0+tx][n0+ty+i]
        WT[(size_t)(n0 + ty + i) * K + k0 + tx] = __uint_as_float(f2tf32(v));
    }
}

// ---------------------------------------------------------------------------
// Pipelined tf32 mma.sync GEMM with ldmatrix fragment loads.
// C[M=4096, N] (+epi) = A[4096, K] (fp32, cvt post-LDSM) @ WT[N, K]^T (pre-rounded tf32)
// Both smem tiles: 128 rows x 32 floats (128B), XOR-swizzled for conflict-free LDSM.
// ---------------------------------------------------------------------------
__global__ __launch_bounds__(256, 2) void gemm_epi(
    const float* __restrict__ A, const float* __restrict__ WT,
    int K, int ldw, int N, EpiParams ep)
{
    extern __shared__ char smem_raw[];
    const uint32_t sA0 = smem_u32(smem_raw);
    const uint32_t sB0 = sA0 + 2 * A_STAGE_B;

    const int m0 = blockIdx.y * BM;
    const int n0 = blockIdx.x * BN;
    const int tid  = threadIdx.x;
    const int lane = tid & 31;
    const int wid  = tid >> 5;
    const int wm = (wid & 3) * 32;   // 4 warps along M
    const int wn = (wid >> 2) * 64;  // 2 warps along N

    // Loader coords: 128 rows x 8 chunks(16B) per tile, 4 chunks/thread
    const int ar = tid >> 3, ac = tid & 7;

    const float* Abase = A + (size_t)m0 * K;
    const float* Bbase = WT + (size_t)n0 * ldw;

    // LDSM per-lane row coords
    const int q  = lane >> 3;       // which 8-lane address group
    const int rr = lane & 7;
    const int cbA = q >> 1;         // A chunk parity offset
    const int cbB = q & 1;          // B chunk parity offset
    const int mArow[2] = { wm + ((q & 1) << 3) + rr,
                           wm + 16 + ((q & 1) << 3) + rr };
    int nBrow[4];
    #pragma unroll
    for (int p = 0; p < 4; p++) nBrow[p] = wn + p * 16 + ((q >> 1) << 3) + rr;

    float accr[2][8][4];
    #pragma unroll
    for (int i = 0; i < 2; i++)
        #pragma unroll
        for (int j = 0; j < 8; j++)
            #pragma unroll
            for (int k = 0; k < 4; k++) accr[i][j][k] = 0.f;

    const int KT = K / BK;

    auto issue_tile = [&](int kt, int st) {
        const uint32_t sa = sA0 + st * A_STAGE_B;
        const uint32_t sb = sB0 + st * B_STAGE_B;
        const float* Ab = Abase + (size_t)kt * BK;
        const float* Bb = Bbase + (size_t)kt * BK;
        #pragma unroll
        for (int i = 0; i < 4; i++) {
            int r = ar + i * 32;
            uint32_t off = (uint32_t)(r * 128) + ((uint32_t)(ac ^ (r & 7)) << 4);
            cpa16(sa + off, Ab + (size_t)r * K + ac * 4);
            cpa16(sb + off, Bb + (size_t)r * ldw + ac * 4);
        }
        cpa_commit();
    };

    issue_tile(0, 0);

    for (int kt = 0; kt < KT; kt++) {
        const int st = kt & 1;
        cpa_wait0();
        __syncthreads();
        if (kt + 1 < KT) issue_tile(kt + 1, (kt + 1) & 1);

        const uint32_t sa = sA0 + st * A_STAGE_B;
        const uint32_t sb = sB0 + st * B_STAGE_B;

        #pragma unroll
        for (int k8 = 0; k8 < 4; k8++) {
            // A fragments: 2 ldmatrix.x4 (one per m16 tile), then rna cvt
            uint32_t af[2][4];
            #pragma unroll
            for (int mt = 0; mt < 2; mt++) {
                int m = mArow[mt];
                uint32_t addr = sa + (uint32_t)(m * 128)
                              + ((uint32_t)((2 * k8 + cbA) ^ (m & 7)) << 4);
                ldsm_x4(af[mt][0], af[mt][1], af[mt][2], af[mt][3], addr);
            }
            #pragma unroll
            for (int mt = 0; mt < 2; mt++)
                #pragma unroll
                for (int j = 0; j < 4; j++)
                    af[mt][j] = f2tf32(__uint_as_float(af[mt][j]));

            // B fragments: 4 ldmatrix.x4, each covering two n8 tiles (pre-rounded)
            uint32_t bf[8][2];
            #pragma unroll
            for (int p = 0; p < 4; p++) {
                int n = nBrow[p];
                uint32_t addr = sb + (uint32_t)(n * 128)
                              + ((uint32_t)((2 * k8 + cbB) ^ (n & 7)) << 4);
                ldsm_x4(bf[2 * p][0], bf[2 * p][1], bf[2 * p + 1][0], bf[2 * p + 1][1], addr);
            }

            #pragma unroll
            for (int mt = 0; mt < 2; mt++)
                #pragma unroll
                for (int nt = 0; nt < 8; nt++)
                    mma_tf32(accr[mt][nt], af[mt], bf[nt]);
        }
    }

    // ---------------- Epilogue ----------------
    float ca = 0.f, cb = 0.f;
    if (ep.mode >= 2 && ep.mode <= 4) {
        float dt = ep.tgrid[ep.step + 1] - ep.tgrid[ep.step];
        ca = ep.fa * dt;
        cb = ep.fb * dt;
    }

    #pragma unroll
    for (int mt = 0; mt < 2; mt++)
        #pragma unroll
        for (int nt = 0; nt < 8; nt++)
            #pragma unroll
            for (int ci = 0; ci < 4; ci++) {
                int row = m0 + wm + mt * 16 + (lane >> 2) + ((ci & 2) << 2);
                int col = n0 + wn + nt * 8 + ((lane & 3) << 1) + (ci & 1);
                size_t idx = (size_t)row * N + col;
                float v = accr[mt][nt][ci];
                switch (ep.mode) {
                    case 0: ep.out1[idx] = v + ep.bias[col]; break;
                    case 1: ep.out1[idx] = tanhf(v + ep.bias[col]); break;
                    case 2: {
                        float k = v + ep.bias[col];
                        float hb = ep.aux1[idx];
                        ep.out1[idx] = hb + ca * k;
                        ep.out2[idx] = hb + cb * k;
                    } break;
                    case 3: {
                        float k = v + ep.bias[col];
                        float hb = ep.aux1[idx];
                        ep.out1[idx] += ca * k;
                        ep.out2[idx] = hb + cb * k;
                    } break;
                    case 4: {
                        float k = v + ep.bias[col];
                        ep.out1[idx] = ep.aux1[idx] + ca * k;
                    } break;
                    case 5: {
                        float pre = v + ep.aux1[idx];
                        ep.out1[idx] = sigm(pre);
                    } break;
                    case 6: {
                        float pre = v + ep.aux1[idx];
                        float ct = sigm(pre);
                        float g = ep.aux2[idx];
                        float cn = g * (ep.aux3[idx] + ct);
                        float hn = g * tanhf(cn);
                        ep.out1[idx] = cn;
                        ep.out2[idx] = hn;
                        ep.out3[idx] = hn;
                    } break;
                }
            }
}

// ---------------------------------------------------------------------------
// Host orchestration
// ---------------------------------------------------------------------------
static inline void run_gemm(const float* A, const float* WT, int K, int ldw, int N,
                            const EpiParams& ep) {
    dim3 grid(N / BN, NB / BM), blk(256);
    gemm_epi<<<grid, blk, SMEM_TOTAL>>>(A, WT, K, ldw, N, ep);
}

extern "C" void kernel_launch(void* const* d_in, const int* in_sizes, int n_in,
                              void* d_out, int out_size) {
    const float* x     = (const float*)d_in[0];
    const float* h     = (const float*)d_in[1];
    const float* c     = (const float*)d_in[2];
    const float* t     = (const float*)d_in[3];
    const float* W_i2h = (const float*)d_in[4];
    const float* b_i2h = (const float*)d_in[5];
    const float* W_h2o = (const float*)d_in[6];
    const float* b_h2o = (const float*)d_in[7];
    const float* Wf1   = (const float*)d_in[8];
    const float* bf1   = (const float*)d_in[9];
    const float* Wf2   = (const float*)d_in[10];
    const float* bf2   = (const float*)d_in[11];

    float* out   = (float*)d_out;
    float* out_o = out;
    float* out_h = out + (size_t)NB * DOUT;
    float* out_c = out + (size_t)NB * DOUT + (size_t)NB * DH;

    cudaFuncSetAttribute(gemm_epi, cudaFuncAttributeMaxDynamicSharedMemorySize, SMEM_TOTAL);

    float *xw, *gate, *hcur, *acc, *arg, *u, *hbuf;
    float *wi2hT, *wf1T, *wf2T, *wh2oT;
    cudaGetSymbolAddress((void**)&xw,    g_xw);
    cudaGetSymbolAddress((void**)&gate,  g_gate);
    cudaGetSymbolAddress((void**)&hcur,  g_hcur);
    cudaGetSymbolAddress((void**)&acc,   g_acc);
    cudaGetSymbolAddress((void**)&arg,   g_arg);
    cudaGetSymbolAddress((void**)&u,     g_u);
    cudaGetSymbolAddress((void**)&hbuf,  g_hbuf);
    cudaGetSymbolAddress((void**)&wi2hT, g_wi2hT);
    cudaGetSymbolAddress((void**)&wf1T,  g_wf1T);
    cudaGetSymbolAddress((void**)&wf2T,  g_wf2T);
    cudaGetSymbolAddress((void**)&wh2oT, g_wh2oT);

    // Prep: transpose + rna-round weights (W[K,N] -> WT[N,K])
    {
        dim3 blk(32, 8);
        transpose_cvt<<<dim3(DH / 32, (DOBS + DH) / 32), blk>>>(W_i2h, wi2hT, DOBS + DH, DH);
        transpose_cvt<<<dim3(DH / 32, DH / 32), blk>>>(Wf1, wf1T, DH, DH);
        transpose_cvt<<<dim3(DH / 32, DH / 32), blk>>>(Wf2, wf2T, DH, DH);
        transpose_cvt<<<dim3(DOUT / 32, DH / 32), blk>>>(W_h2o, wh2oT, DH, DOUT);
    }

    const int LDW = DOBS + DH;              // 1280: row stride of wi2hT
    const float* wbotT = wi2hT + DOBS;      // k-offset 256 within each row

    // 1) xw = x @ W_i2h[:256] + b_i2h
    {
        EpiParams ep{}; ep.bias = b_i2h; ep.out1 = xw; ep.mode = 0;
        run_gemm(x, wi2hT, DOBS, LDW, DH, ep);
    }
    // 2) gate = sigmoid(xw + h @ W_bot)
    {
        EpiParams ep{}; ep.aux1 = xw; ep.out1 = gate; ep.mode = 5;
        run_gemm(h, wbotT, DH, LDW, DH, ep);
    }
    // 3) RK4
    for (int s = 0; s < NTT - 1; s++) {
        const float* hb = (s == 0) ? h : hcur;
        { EpiParams ep{}; ep.bias = bf1; ep.out1 = u; ep.mode = 1;
          run_gemm(hb, wf1T, DH, DH, DH, ep); }
        { EpiParams ep{}; ep.bias = bf2; ep.tgrid = t; ep.step = s;
          ep.fa = 1.f / 6.f; ep.fb = 0.5f; ep.aux1 = hb;
          ep.out1 = acc; ep.out2 = arg; ep.mode = 2;
          run_gemm(u, wf2T, DH, DH, DH, ep); }
        { EpiParams ep{}; ep.bias = bf1; ep.out1 = u; ep.mode = 1;
          run_gemm(arg, wf1T, DH, DH, DH, ep); }
        { EpiParams ep{}; ep.bias = bf2; ep.tgrid = t; ep.step = s;
          ep.fa = 1.f / 3.f; ep.fb = 0.5f; ep.aux1 = hb;
          ep.out1 = acc; ep.out2 = arg; ep.mode = 3;
          run_gemm(u, wf2T, DH, DH, DH, ep); }
        { EpiParams ep{}; ep.bias = bf1; ep.out1 = u; ep.mode = 1;
          run_gemm(arg, wf1T, DH, DH, DH, ep); }
        { EpiParams ep{}; ep.bias = bf2; ep.tgrid = t; ep.step = s;
          ep.fa = 1.f / 3.f; ep.fb = 1.0f; ep.aux1 = hb;
          ep.out1 = acc; ep.out2 = arg; ep.mode = 3;
          run_gemm(u, wf2T, DH, DH, DH, ep); }
        { EpiParams ep{}; ep.bias = bf1; ep.out1 = u; ep.mode = 1;
          run_gemm(arg, wf1T, DH, DH, DH, ep); }
        { EpiParams ep{}; ep.bias = bf2; ep.tgrid = t; ep.step = s;
          ep.fa = 1.f / 6.f; ep.fb = 0.f; ep.aux1 = acc;
          ep.out1 = hcur; ep.mode = 4;
          run_gemm(u, wf2T, DH, DH, DH, ep); }
    }
    // 4) c_tilde + fused LSTM recombine
    {
        EpiParams ep{}; ep.aux1 = xw; ep.aux2 = gate; ep.aux3 = c;
        ep.out1 = out_c; ep.out2 = out_h; ep.out3 = hbuf; ep.mode = 6;
        run_gemm(hcur, wbotT, DH, LDW, DH, ep);
    }
    // 5) out = h_new @ W_h2o + b_h2o
    {
        EpiParams ep{}; ep.bias = b_h2o; ep.out1 = out_o; ep.mode = 0;
        run_gemm(hbuf, wh2oT, DH, DH, DOUT, ep);
    }
}